// round 2
// baseline (speedup 1.0000x reference)
#include <cuda_runtime.h>

#define BB   4
#define CCH  64
#define HH   180
#define WWD  320
#define HWP  (HH*WWD)        // 57600
#define NPIX (BB*HWP)        // 230400
#define NELT ((size_t)NPIX*CCH)   // 14,745,600

// Scratch (static device globals: allowed; runtime allocs are not)
__device__ float g_Ql[NPIX*CCH];
__device__ float g_Qr[NPIX*CCH];
__device__ float g_Vl[NPIX*CCH];
__device__ float g_Vr[NPIX*CCH];
__device__ float g_attn[(size_t)BB*HH*WWD*WWD];   // 294.9 MB

// ---------------------------------------------------------------------------
// Kernel P: per 64-pixel tile, LayerNorm + Q projection (on LN'd x) + V
// projection (on raw x). One kernel per side (side selects output buffers).
// ---------------------------------------------------------------------------
__global__ __launch_bounds__(256) void proj_kernel(
    const float* __restrict__ x,
    const float* __restrict__ lnw, const float* __restrict__ lnb,
    const float* __restrict__ wq,  const float* __restrict__ bq,
    const float* __restrict__ wv,  const float* __restrict__ bv,
    int side)
{
    __shared__ float xs[64][68];
    __shared__ float wT[64][68];
    __shared__ float mu_s[64], rs_s[64];

    float* Qo = side ? g_Qr : g_Ql;
    float* Vo = side ? g_Vr : g_Vl;

    int tid = threadIdx.x;
    int pb  = blockIdx.x * 64;        // tile never crosses batch: HWP % 64 == 0
    int b   = pb / HWP;
    int q0  = pb - b * HWP;
    const float* xb = x + ((size_t)b * CCH) * HWP + q0;

    // load x tile [c][p] (coalesced) and wv transposed [c][o]
    #pragma unroll
    for (int i = 0; i < 16; i++) {
        int idx = i * 256 + tid;
        int c = idx >> 6, p = idx & 63;
        xs[c][p] = xb[(size_t)c * HWP + p];
        wT[idx & 63][idx >> 6] = wv[idx];
    }
    __syncthreads();

    // LayerNorm stats over channels, per pixel
    if (tid < 64) {
        float s = 0.f, ss = 0.f;
        #pragma unroll
        for (int c = 0; c < 64; c++) { float v = xs[c][tid]; s += v; ss += v*v; }
        float m = s * 0.015625f;
        mu_s[tid] = m;
        rs_s[tid] = rsqrtf(ss * 0.015625f - m*m + 1e-6f);
    }
    __syncthreads();

    int ox = tid >> 4, px = tid & 15;  // o = 4*ox+i, p = 4*px+j
    int o0 = 4 * ox;

    // ---- V = wv @ x ----
    {
        float acc[4][4];
        #pragma unroll
        for (int i = 0; i < 4; i++)
            #pragma unroll
            for (int j = 0; j < 4; j++) acc[i][j] = 0.f;
        #pragma unroll 8
        for (int c = 0; c < 64; c++) {
            float4 w4 = *(const float4*)&wT[c][4*ox];
            float4 x4 = *(const float4*)&xs[c][4*px];
            float wa[4] = {w4.x, w4.y, w4.z, w4.w};
            float xa[4] = {x4.x, x4.y, x4.z, x4.w};
            #pragma unroll
            for (int i = 0; i < 4; i++)
                #pragma unroll
                for (int j = 0; j < 4; j++) acc[i][j] += wa[i] * xa[j];
        }
        #pragma unroll
        for (int i = 0; i < 4; i++) {
            float bias = bv[o0 + i];
            float4 r = make_float4(acc[i][0]+bias, acc[i][1]+bias,
                                   acc[i][2]+bias, acc[i][3]+bias);
            *(float4*)&Vo[((size_t)(b*CCH + o0 + i)) * HWP + q0 + 4*px] = r;
        }
    }
    __syncthreads();

    // overwrite weights with wq, normalize xs in place
    #pragma unroll
    for (int i = 0; i < 16; i++) {
        int idx = i * 256 + tid;
        wT[idx & 63][idx >> 6] = wq[idx];
    }
    #pragma unroll
    for (int i = 0; i < 16; i++) {
        int idx = i * 256 + tid;
        int c = idx >> 6, p = idx & 63;
        xs[c][p] = (xs[c][p] - mu_s[p]) * rs_s[p] * lnw[c] + lnb[c];
    }
    __syncthreads();

    // ---- Q = wq @ LN(x) ----
    {
        float acc[4][4];
        #pragma unroll
        for (int i = 0; i < 4; i++)
            #pragma unroll
            for (int j = 0; j < 4; j++) acc[i][j] = 0.f;
        #pragma unroll 8
        for (int c = 0; c < 64; c++) {
            float4 w4 = *(const float4*)&wT[c][4*ox];
            float4 x4 = *(const float4*)&xs[c][4*px];
            float wa[4] = {w4.x, w4.y, w4.z, w4.w};
            float xa[4] = {x4.x, x4.y, x4.z, x4.w};
            #pragma unroll
            for (int i = 0; i < 4; i++)
                #pragma unroll
                for (int j = 0; j < 4; j++) acc[i][j] += wa[i] * xa[j];
        }
        #pragma unroll
        for (int i = 0; i < 4; i++) {
            float bias = bq[o0 + i];
            float4 r = make_float4(acc[i][0]+bias, acc[i][1]+bias,
                                   acc[i][2]+bias, acc[i][3]+bias);
            *(float4*)&Qo[((size_t)(b*CCH + o0 + i)) * HWP + q0 + 4*px] = r;
        }
    }
}

// ---------------------------------------------------------------------------
// Kernel A: attn[bh][wl][wr] = scale * sum_c Ql[c][wl] * Qr[c][wr]
// One block per (b,h). Q rows live in smem (160 KB).
// ---------------------------------------------------------------------------
__global__ __launch_bounds__(256) void attn_kernel()
{
    extern __shared__ float sm[];
    float* Qls = sm;               // [64][320]
    float* Qrs = sm + 64*320;      // [64][320]

    int tid = threadIdx.x;
    int bh = blockIdx.x;
    int b = bh / HH, h = bh - b * HH;
    const float* qlb = g_Ql + ((size_t)b * CCH) * HWP + h * WWD;
    const float* qrb = g_Qr + ((size_t)b * CCH) * HWP + h * WWD;

    #pragma unroll 4
    for (int i = 0; i < 80; i++) {
        int idx = i * 256 + tid;
        int c = idx / 320, w = idx - c * 320;
        Qls[idx] = qlb[(size_t)c * HWP + w];
        Qrs[idx] = qrb[(size_t)c * HWP + w];
    }
    __syncthreads();

    float* ap = g_attn + (size_t)bh * (WWD * WWD);
    int rx = tid >> 4, px = tid & 15;

    #pragma unroll 1
    for (int ti = 0; ti < 5; ti++) {
        #pragma unroll 1
        for (int tj = 0; tj < 5; tj++) {
            int wl = ti * 64 + 4 * rx;
            int wr = tj * 64 + 4 * px;
            float acc[4][4];
            #pragma unroll
            for (int i = 0; i < 4; i++)
                #pragma unroll
                for (int j = 0; j < 4; j++) acc[i][j] = 0.f;
            #pragma unroll 8
            for (int k = 0; k < 64; k++) {
                float4 a4 = *(const float4*)&Qls[k * 320 + wl];
                float4 b4 = *(const float4*)&Qrs[k * 320 + wr];
                float aa[4] = {a4.x, a4.y, a4.z, a4.w};
                float bb[4] = {b4.x, b4.y, b4.z, b4.w};
                #pragma unroll
                for (int i = 0; i < 4; i++)
                    #pragma unroll
                    for (int j = 0; j < 4; j++) acc[i][j] += aa[i] * bb[j];
            }
            #pragma unroll
            for (int i = 0; i < 4; i++) {
                float4 r = make_float4(acc[i][0]*0.125f, acc[i][1]*0.125f,
                                       acc[i][2]*0.125f, acc[i][3]*0.125f);
                *(float4*)&ap[(wl + i) * 320 + wr] = r;
            }
        }
    }
}

// ---------------------------------------------------------------------------
// Kernel B: row softmax over wr, F = P @ Vr^T, out_l = x_l + beta*F
// ---------------------------------------------------------------------------
__global__ __launch_bounds__(256) void r2l_kernel(
    const float* __restrict__ x_l, const float* __restrict__ beta,
    float* __restrict__ out_l)
{
    extern __shared__ float sm[];
    float* VrT  = sm;                        // [320][68] : [v][c]
    float* Pt   = sm + 320*68;               // [64][68]  : [v_local][wl_local]
    float* rmax = sm + 320*68 + 64*68;       // [320]
    float* rinv = rmax + 320;

    int tid = threadIdx.x;
    int bh = blockIdx.x;
    int b = bh / HH, h = bh - b * HH;
    const float* vrb = g_Vr + ((size_t)b * CCH) * HWP + h * WWD;

    #pragma unroll 4
    for (int i = 0; i < 80; i++) {
        int idx = i * 256 + tid;
        int c = idx / 320, v = idx - c * 320;
        VrT[v * 68 + c] = vrb[(size_t)c * HWP + v];
    }

    const float* ap = g_attn + (size_t)bh * (WWD * WWD);
    int wid = tid >> 5, lane = tid & 31;
    for (int row = wid; row < 320; row += 8) {
        const float* rp = ap + row * 320;
        float a[10], m = -1e30f;
        #pragma unroll
        for (int j = 0; j < 10; j++) { a[j] = rp[lane + 32*j]; m = fmaxf(m, a[j]); }
        #pragma unroll
        for (int o = 16; o > 0; o >>= 1) m = fmaxf(m, __shfl_xor_sync(0xffffffffu, m, o));
        float s = 0.f;
        #pragma unroll
        for (int j = 0; j < 10; j++) s += __expf(a[j] - m);
        #pragma unroll
        for (int o = 16; o > 0; o >>= 1) s += __shfl_xor_sync(0xffffffffu, s, o);
        if (lane == 0) { rmax[row] = m; rinv[row] = 1.0f / s; }
    }
    __syncthreads();

    int cx = tid >> 4, px = tid & 15;   // c = 4cx+i, wl_local = 4px+j
    const float* xb = x_l + ((size_t)b * CCH) * HWP + h * WWD;
    float* ob = out_l + ((size_t)b * CCH) * HWP + h * WWD;

    #pragma unroll 1
    for (int wt = 0; wt < 5; wt++) {
        int wl0 = wt * 64;
        float acc[4][4];
        #pragma unroll
        for (int i = 0; i < 4; i++)
            #pragma unroll
            for (int j = 0; j < 4; j++) acc[i][j] = 0.f;

        #pragma unroll 1
        for (int vt = 0; vt < 5; vt++) {
            __syncthreads();
            #pragma unroll
            for (int i = 0; i < 16; i++) {
                int idx = i * 256 + tid;
                int r = idx >> 6, vc = idx & 63;
                float av = ap[(wl0 + r) * 320 + vt * 64 + vc];
                Pt[vc * 68 + r] = __expf(av - rmax[wl0 + r]) * rinv[wl0 + r];
            }
            __syncthreads();
            #pragma unroll 8
            for (int v = 0; v < 64; v++) {
                float4 p4 = *(const float4*)&Pt[v * 68 + 4 * px];
                float4 v4 = *(const float4*)&VrT[(vt * 64 + v) * 68 + 4 * cx];
                float pa[4] = {p4.x, p4.y, p4.z, p4.w};
                float va[4] = {v4.x, v4.y, v4.z, v4.w};
                #pragma unroll
                for (int i = 0; i < 4; i++)
                    #pragma unroll
                    for (int j = 0; j < 4; j++) acc[i][j] += va[i] * pa[j];
            }
        }
        #pragma unroll
        for (int i = 0; i < 4; i++) {
            int c = 4 * cx + i;
            float bt = beta[c];
            float4 xv = *(const float4*)&xb[(size_t)c * HWP + wl0 + 4 * px];
            float4 r = make_float4(xv.x + bt*acc[i][0], xv.y + bt*acc[i][1],
                                   xv.z + bt*acc[i][2], xv.w + bt*acc[i][3]);
            *(float4*)&ob[(size_t)c * HWP + wl0 + 4 * px] = r;
        }
    }
}

// ---------------------------------------------------------------------------
// Kernel C: column softmax over wl, F = P2^T-weighted Vl, out_r = x_r + gamma*F
// ---------------------------------------------------------------------------
__global__ __launch_bounds__(256) void l2r_kernel(
    const float* __restrict__ x_r, const float* __restrict__ gamma,
    float* __restrict__ out_r)
{
    extern __shared__ float sm[];
    float* VlT  = sm;                        // [320][68] : [wl][c]
    float* Ps   = sm + 320*68;               // [64][68]  : [wl_local][wr_local]
    float* cmax = sm + 320*68 + 64*68;       // [320]
    float* cinv = cmax + 320;

    int tid = threadIdx.x;
    int bh = blockIdx.x;
    int b = bh / HH, h = bh - b * HH;
    const float* vlb = g_Vl + ((size_t)b * CCH) * HWP + h * WWD;

    #pragma unroll 4
    for (int i = 0; i < 80; i++) {
        int idx = i * 256 + tid;
        int c = idx / 320, w = idx - c * 320;
        VlT[w * 68 + c] = vlb[(size_t)c * HWP + w];
    }

    const float* ap = g_attn + (size_t)bh * (WWD * WWD);
    // column stats: thread tid owns column tid (all) and 256+tid (tid<64)
    {
        float m1 = -1e30f, m2 = -1e30f;
        for (int row = 0; row < 320; row++) {
            const float* rp = ap + row * 320;
            m1 = fmaxf(m1, rp[tid]);
            if (tid < 64) m2 = fmaxf(m2, rp[256 + tid]);
        }
        float s1 = 0.f, s2 = 0.f;
        for (int row = 0; row < 320; row++) {
            const float* rp = ap + row * 320;
            s1 += __expf(rp[tid] - m1);
            if (tid < 64) s2 += __expf(rp[256 + tid] - m2);
        }
        cmax[tid] = m1; cinv[tid] = 1.0f / s1;
        if (tid < 64) { cmax[256 + tid] = m2; cinv[256 + tid] = 1.0f / s2; }
    }
    __syncthreads();

    int cx = tid >> 4, px = tid & 15;   // c = 4cx+i, wr_local = 4px+j
    const float* xb = x_r + ((size_t)b * CCH) * HWP + h * WWD;
    float* ob = out_r + ((size_t)b * CCH) * HWP + h * WWD;

    #pragma unroll 1
    for (int wrt = 0; wrt < 5; wrt++) {
        int wr0 = wrt * 64;
        float acc[4][4];
        #pragma unroll
        for (int i = 0; i < 4; i++)
            #pragma unroll
            for (int j = 0; j < 4; j++) acc[i][j] = 0.f;

        #pragma unroll 1
        for (int wlt = 0; wlt < 5; wlt++) {
            __syncthreads();
            #pragma unroll
            for (int i = 0; i < 16; i++) {
                int idx = i * 256 + tid;
                int r = idx >> 6, vc = idx & 63;
                float av = ap[(wlt * 64 + r) * 320 + wr0 + vc];
                Ps[r * 68 + vc] = __expf(av - cmax[wr0 + vc]) * cinv[wr0 + vc];
            }
            __syncthreads();
            #pragma unroll 8
            for (int k = 0; k < 64; k++) {
                float4 p4 = *(const float4*)&Ps[k * 68 + 4 * px];
                float4 v4 = *(const float4*)&VlT[(wlt * 64 + k) * 68 + 4 * cx];
                float pa[4] = {p4.x, p4.y, p4.z, p4.w};
                float va[4] = {v4.x, v4.y, v4.z, v4.w};
                #pragma unroll
                for (int i = 0; i < 4; i++)
                    #pragma unroll
                    for (int j = 0; j < 4; j++) acc[i][j] += va[i] * pa[j];
            }
        }
        #pragma unroll
        for (int i = 0; i < 4; i++) {
            int c = 4 * cx + i;
            float gm = gamma[c];
            float4 xv = *(const float4*)&xb[(size_t)c * HWP + wr0 + 4 * px];
            float4 r = make_float4(xv.x + gm*acc[i][0], xv.y + gm*acc[i][1],
                                   xv.z + gm*acc[i][2], xv.w + gm*acc[i][3]);
            *(float4*)&ob[(size_t)c * HWP + wr0 + 4 * px] = r;
        }
    }
}

// ---------------------------------------------------------------------------
extern "C" void kernel_launch(void* const* d_in, const int* in_sizes, int n_in,
                              void* d_out, int out_size)
{
    const float* x_l    = (const float*)d_in[0];
    const float* x_r    = (const float*)d_in[1];
    const float* ln_l_w = (const float*)d_in[2];
    const float* ln_l_b = (const float*)d_in[3];
    const float* ln_r_w = (const float*)d_in[4];
    const float* ln_r_b = (const float*)d_in[5];
    const float* wq_l   = (const float*)d_in[6];
    const float* bq_l   = (const float*)d_in[7];
    const float* wq_r   = (const float*)d_in[8];
    const float* bq_r   = (const float*)d_in[9];
    const float* wv_l   = (const float*)d_in[10];
    const float* bv_l   = (const float*)d_in[11];
    const float* wv_r   = (const float*)d_in[12];
    const float* bv_r   = (const float*)d_in[13];
    const float* beta   = (const float*)d_in[14];
    const float* gamma  = (const float*)d_in[15];

    float* out_l = (float*)d_out;
    float* out_r = out_l + NELT;

    cudaFuncSetAttribute(attn_kernel, cudaFuncAttributeMaxDynamicSharedMemorySize, 163840);
    cudaFuncSetAttribute(r2l_kernel,  cudaFuncAttributeMaxDynamicSharedMemorySize, 107008);
    cudaFuncSetAttribute(l2r_kernel,  cudaFuncAttributeMaxDynamicSharedMemorySize, 107008);

    proj_kernel<<<NPIX/64, 256>>>(x_l, ln_l_w, ln_l_b, wq_l, bq_l, wv_l, bv_l, 0);
    proj_kernel<<<NPIX/64, 256>>>(x_r, ln_r_w, ln_r_b, wq_r, bq_r, wv_r, bv_r, 1);
    attn_kernel<<<BB*HH, 256, 163840>>>();
    r2l_kernel<<<BB*HH, 256, 107008>>>(x_l, beta, out_l);
    l2r_kernel<<<BB*HH, 256, 107008>>>(x_r, gamma, out_r);
}

// round 5
// speedup vs baseline: 2.6947x; 2.6947x over previous
#include <cuda_runtime.h>
#include <cstdint>

#define BB   4
#define CCH  64
#define HH   180
#define WWD  320
#define HWP  (HH*WWD)
#define NPIX (BB*HWP)
#define NELT ((size_t)NPIX*CCH)

__device__ float g_QlT[(size_t)NPIX*CCH];   // [pix][c]
__device__ float g_Qr [(size_t)NPIX*CCH];   // [c][pix]
__device__ float g_Vl [(size_t)NPIX*CCH];   // [c][pix]
__device__ float g_VrT[(size_t)NPIX*CCH];   // [pix][c]
__device__ float g_E[(size_t)BB*HH*WWD*WWD];

__device__ __forceinline__ uint32_t f2tf(float x){
    uint32_t u; asm("cvt.rna.tf32.f32 %0, %1;" : "=r"(u) : "f"(x)); return u;
}
__device__ __forceinline__ void mma_tf32(float d[4], const uint32_t a[4], const uint32_t b[2]){
    asm volatile("mma.sync.aligned.m16n8k8.row.col.f32.tf32.tf32.f32 "
                 "{%0,%1,%2,%3}, {%4,%5,%6,%7}, {%8,%9}, {%0,%1,%2,%3};"
                 : "+f"(d[0]), "+f"(d[1]), "+f"(d[2]), "+f"(d[3])
                 : "r"(a[0]), "r"(a[1]), "r"(a[2]), "r"(a[3]), "r"(b[0]), "r"(b[1]));
}

// ---------------- projection ----------------
__global__ __launch_bounds__(256) void proj_kernel(
    const float* __restrict__ x,
    const float* __restrict__ lnw, const float* __restrict__ lnb,
    const float* __restrict__ wq,  const float* __restrict__ bq,
    const float* __restrict__ wv,  const float* __restrict__ bv,
    int side)
{
    __shared__ float xs[64][68];
    __shared__ float wT[64][68];
    __shared__ float mu_s[64], rs_s[64];

    float* Qo = side ? g_Qr  : g_QlT;
    float* Vo = side ? g_VrT : g_Vl;

    int tid = threadIdx.x;
    int pb  = blockIdx.x * 64;
    int b   = pb / HWP;
    int q0  = pb - b * HWP;
    const float* xb = x + ((size_t)b * CCH) * HWP + q0;

    #pragma unroll
    for (int i = 0; i < 16; i++) {
        int idx = i * 256 + tid;
        int c = idx >> 6, p = idx & 63;
        xs[c][p] = xb[(size_t)c * HWP + p];
        wT[idx & 63][idx >> 6] = wv[idx];
    }
    __syncthreads();
    if (tid < 64) {
        float s = 0.f, ss = 0.f;
        #pragma unroll
        for (int c = 0; c < 64; c++) { float v = xs[c][tid]; s += v; ss += v*v; }
        float m = s * 0.015625f;
        mu_s[tid] = m;
        rs_s[tid] = rsqrtf(ss * 0.015625f - m*m + 1e-6f);
    }
    __syncthreads();

    int ox = tid >> 4, px = tid & 15, o0 = 4 * ox;

    { // V = wv @ x
        float acc[4][4];
        #pragma unroll
        for (int i = 0; i < 4; i++)
            #pragma unroll
            for (int j = 0; j < 4; j++) acc[i][j] = 0.f;
        #pragma unroll 8
        for (int c = 0; c < 64; c++) {
            float4 w4 = *(const float4*)&wT[c][4*ox];
            float4 x4 = *(const float4*)&xs[c][4*px];
            float wa[4] = {w4.x, w4.y, w4.z, w4.w};
            float xa[4] = {x4.x, x4.y, x4.z, x4.w};
            #pragma unroll
            for (int i = 0; i < 4; i++)
                #pragma unroll
                for (int j = 0; j < 4; j++) acc[i][j] += wa[i] * xa[j];
        }
        if (side == 0) {
            #pragma unroll
            for (int i = 0; i < 4; i++) {
                float bias = bv[o0 + i];
                float4 r = make_float4(acc[i][0]+bias, acc[i][1]+bias,
                                       acc[i][2]+bias, acc[i][3]+bias);
                *(float4*)&Vo[((size_t)(b*CCH + o0 + i)) * HWP + q0 + 4*px] = r;
            }
        } else {
            __syncthreads();
            #pragma unroll
            for (int i = 0; i < 4; i++) {
                float bias = bv[o0 + i];
                float4 r = make_float4(acc[i][0]+bias, acc[i][1]+bias,
                                       acc[i][2]+bias, acc[i][3]+bias);
                *(float4*)&wT[o0 + i][4*px] = r;
            }
            __syncthreads();
            #pragma unroll
            for (int i = 0; i < 16; i++) {
                int idx = i * 256 + tid;
                int p = idx >> 6, c = idx & 63;
                Vo[((size_t)pb + p) * 64 + c] = wT[c][p];
            }
        }
    }
    __syncthreads();

    #pragma unroll
    for (int i = 0; i < 16; i++) {
        int idx = i * 256 + tid;
        wT[idx & 63][idx >> 6] = wq[idx];
    }
    #pragma unroll
    for (int i = 0; i < 16; i++) {
        int idx = i * 256 + tid;
        int c = idx >> 6, p = idx & 63;
        xs[c][p] = (xs[c][p] - mu_s[p]) * rs_s[p] * lnw[c] + lnb[c];
    }
    __syncthreads();

    { // Q = wq @ LN(x)
        float acc[4][4];
        #pragma unroll
        for (int i = 0; i < 4; i++)
            #pragma unroll
            for (int j = 0; j < 4; j++) acc[i][j] = 0.f;
        #pragma unroll 8
        for (int c = 0; c < 64; c++) {
            float4 w4 = *(const float4*)&wT[c][4*ox];
            float4 x4 = *(const float4*)&xs[c][4*px];
            float wa[4] = {w4.x, w4.y, w4.z, w4.w};
            float xa[4] = {x4.x, x4.y, x4.z, x4.w};
            #pragma unroll
            for (int i = 0; i < 4; i++)
                #pragma unroll
                for (int j = 0; j < 4; j++) acc[i][j] += wa[i] * xa[j];
        }
        if (side == 1) {
            #pragma unroll
            for (int i = 0; i < 4; i++) {
                float bias = bq[o0 + i];
                float4 r = make_float4(acc[i][0]+bias, acc[i][1]+bias,
                                       acc[i][2]+bias, acc[i][3]+bias);
                *(float4*)&Qo[((size_t)(b*CCH + o0 + i)) * HWP + q0 + 4*px] = r;
            }
        } else {
            __syncthreads();
            #pragma unroll
            for (int i = 0; i < 4; i++) {
                float bias = bq[o0 + i];
                float4 r = make_float4(acc[i][0]+bias, acc[i][1]+bias,
                                       acc[i][2]+bias, acc[i][3]+bias);
                *(float4*)&wT[o0 + i][4*px] = r;
            }
            __syncthreads();
            #pragma unroll
            for (int i = 0; i < 16; i++) {
                int idx = i * 256 + tid;
                int p = idx >> 6, c = idx & 63;
                Qo[((size_t)pb + p) * 64 + c] = wT[c][p];
            }
        }
    }
}

// ---------------- fused attention per (b,h) ----------------
__global__ __launch_bounds__(256, 1) void fused_attn_kernel(
    const float* __restrict__ x_l, const float* __restrict__ x_r,
    const float* __restrict__ beta, const float* __restrict__ gamma,
    float* __restrict__ out_l, float* __restrict__ out_r)
{
    extern __shared__ float sm[];
    float* rs = sm;                 // [320]
    float* cs = sm + 320;           // [320]
    uint32_t* bufA = (uint32_t*)(sm + 640);   // 21760
    uint32_t* bufB = bufA + 21760;            // 21760

    int tid = threadIdx.x, lane = tid & 31, wid = tid >> 5;
    int bh = blockIdx.x, b = bh / HH, h = bh - b * HH;
    size_t pixb = (size_t)b * HWP + h * WWD;
    size_t cmb  = (size_t)b * CCH * HWP + h * WWD;   // channel-major base
    float* Eb = g_E + (size_t)bh * (WWD * WWD);

    for (int i = tid; i < 640; i += 256) sm[i] = 0.f;

    { // QlT -> bufA [320][68]
        const float* src = g_QlT + pixb * 64;
        #pragma unroll
        for (int it = 0; it < 20; it++) {
            int e = it * 256 + tid, wl = e >> 4, c4 = e & 15;
            float4 v = *(const float4*)(src + (size_t)wl * 64 + c4 * 4);
            *(uint4*)(bufA + wl * 68 + c4 * 4) =
                make_uint4(f2tf(v.x), f2tf(v.y), f2tf(v.z), f2tf(v.w));
        }
    }
    { // Qr -> bufB [64][328]
        const float* src = g_Qr + cmb;
        #pragma unroll
        for (int it = 0; it < 20; it++) {
            int e = it * 256 + tid, c = e / 80, w4 = e % 80;
            float4 v = *(const float4*)(src + (size_t)c * HWP + w4 * 4);
            *(uint4*)(bufB + c * 328 + w4 * 4) =
                make_uint4(f2tf(v.x), f2tf(v.y), f2tf(v.z), f2tf(v.w));
        }
    }
    __syncthreads();

    // ---- GEMM1: E = exp(0.125 * Ql^T Qr), row/col sums ----
    {
        int wy = wid >> 2, wx = wid & 3, n0 = wx * 80;
        for (int mb = 0; mb < 5; mb++) {
            int m0 = mb * 64 + wy * 32;
            float C[2][10][4];
            #pragma unroll
            for (int mt = 0; mt < 2; mt++)
                #pragma unroll
                for (int nt = 0; nt < 10; nt++)
                    #pragma unroll
                    for (int k = 0; k < 4; k++) C[mt][nt][k] = 0.f;
            #pragma unroll
            for (int ks = 0; ks < 8; ks++) {
                uint32_t a[2][4], bb[10][2];
                #pragma unroll
                for (int mt = 0; mt < 2; mt++) {
                    const uint32_t* p = bufA + (m0 + mt*16 + (lane>>2))*68 + ks*8 + (lane&3);
                    a[mt][0]=p[0]; a[mt][1]=p[8*68]; a[mt][2]=p[4]; a[mt][3]=p[8*68+4];
                }
                #pragma unroll
                for (int nt = 0; nt < 10; nt++) {
                    const uint32_t* p = bufB + (ks*8 + (lane&3))*328 + n0 + nt*8 + (lane>>2);
                    bb[nt][0]=p[0]; bb[nt][1]=p[4*328];
                }
                #pragma unroll
                for (int mt = 0; mt < 2; mt++)
                    #pragma unroll
                    for (int nt = 0; nt < 10; nt++)
                        mma_tf32(C[mt][nt], a[mt], bb[nt]);
            }
            #pragma unroll
            for (int mt = 0; mt < 2; mt++)
                #pragma unroll
                for (int nt = 0; nt < 10; nt++)
                    #pragma unroll
                    for (int k = 0; k < 4; k++)
                        C[mt][nt][k] = __expf(C[mt][nt][k] * 0.125f);
            #pragma unroll
            for (int mt = 0; mt < 2; mt++) {
                int r0 = m0 + mt*16 + (lane>>2);
                float s0 = 0.f, s1 = 0.f;
                #pragma unroll
                for (int nt = 0; nt < 10; nt++) {
                    int col = n0 + nt*8 + 2*(lane&3);
                    float2 lo = make_float2(C[mt][nt][0], C[mt][nt][1]);
                    float2 hi = make_float2(C[mt][nt][2], C[mt][nt][3]);
                    *(float2*)(Eb + (size_t)r0*320 + col)     = lo;
                    *(float2*)(Eb + (size_t)(r0+8)*320 + col) = hi;
                    s0 += lo.x + lo.y; s1 += hi.x + hi.y;
                }
                s0 += __shfl_xor_sync(~0u, s0, 1); s0 += __shfl_xor_sync(~0u, s0, 2);
                s1 += __shfl_xor_sync(~0u, s1, 1); s1 += __shfl_xor_sync(~0u, s1, 2);
                if ((lane & 3) == 0) { atomicAdd(&rs[r0], s0); atomicAdd(&rs[r0+8], s1); }
            }
            #pragma unroll
            for (int nt = 0; nt < 10; nt++) {
                int col = n0 + nt*8 + 2*(lane&3);
                float v0 = C[0][nt][0]+C[0][nt][2]+C[1][nt][0]+C[1][nt][2];
                float v1 = C[0][nt][1]+C[0][nt][3]+C[1][nt][1]+C[1][nt][3];
                v0 += __shfl_xor_sync(~0u, v0, 4); v0 += __shfl_xor_sync(~0u, v0, 8); v0 += __shfl_xor_sync(~0u, v0, 16);
                v1 += __shfl_xor_sync(~0u, v1, 4); v1 += __shfl_xor_sync(~0u, v1, 8); v1 += __shfl_xor_sync(~0u, v1, 16);
                if ((lane >> 2) == 0) { atomicAdd(&cs[col], v0); atomicAdd(&cs[col+1], v1); }
            }
        }
    }
    __syncthreads();
    for (int i = tid; i < 640; i += 256) sm[i] = 1.0f / sm[i];
    __syncthreads();

    // ---- GEMM2 (r2l): C[wl][c] = (E*rinv) @ VrT ----
    {
        const float* src = g_VrT + pixb * 64;   // -> bufB [320][68]
        #pragma unroll
        for (int it = 0; it < 20; it++) {
            int e = it * 256 + tid, w = e >> 4, c4 = e & 15;
            float4 v = *(const float4*)(src + (size_t)w * 64 + c4 * 4);
            *(uint4*)(bufB + w * 68 + c4 * 4) =
                make_uint4(f2tf(v.x), f2tf(v.y), f2tf(v.z), f2tf(v.w));
        }
        int wy = wid >> 1, wx = wid & 1;
        int m0 = wy * 80, n0 = wx * 32;
        float C[5][4][4];
        #pragma unroll
        for (int mt = 0; mt < 5; mt++)
            #pragma unroll
            for (int nt = 0; nt < 4; nt++)
                #pragma unroll
                for (int k = 0; k < 4; k++) C[mt][nt][k] = 0.f;

        for (int kc = 0; kc < 5; kc++) {
            #pragma unroll
            for (int it = 0; it < 20; it++) {   // E*rinv -> bufA [320][68]
                int e = it * 256 + tid, wl = e >> 4, c4 = e & 15;
                float4 v = *(const float4*)(Eb + (size_t)wl * 320 + kc*64 + c4*4);
                float ri = rs[wl];
                *(uint4*)(bufA + wl * 68 + c4 * 4) = make_uint4(
                    f2tf(v.x*ri), f2tf(v.y*ri), f2tf(v.z*ri), f2tf(v.w*ri));
            }
            __syncthreads();
            #pragma unroll
            for (int ks = 0; ks < 8; ks++) {
                uint32_t a[5][4], bb[4][2];
                #pragma unroll
                for (int mt = 0; mt < 5; mt++) {
                    const uint32_t* p = bufA + (m0 + mt*16 + (lane>>2))*68 + ks*8 + (lane&3);
                    a[mt][0]=p[0]; a[mt][1]=p[8*68]; a[mt][2]=p[4]; a[mt][3]=p[8*68+4];
                }
                #pragma unroll
                for (int nt = 0; nt < 4; nt++) {
                    const uint32_t* p = bufB + (kc*64 + ks*8 + (lane&3))*68 + n0 + nt*8 + (lane>>2);
                    bb[nt][0]=p[0]; bb[nt][1]=p[4*68];
                }
                #pragma unroll
                for (int mt = 0; mt < 5; mt++)
                    #pragma unroll
                    for (int nt = 0; nt < 4; nt++)
                        mma_tf32(C[mt][nt], a[mt], bb[nt]);
            }
            __syncthreads();
        }
        // stage C -> bufF[c][wl] (stride 324), then coalesced epilogue
        float* bufF = (float*)bufA;
        #pragma unroll
        for (int mt = 0; mt < 5; mt++) {
            int r = m0 + mt*16 + (lane>>2);
            #pragma unroll
            for (int nt = 0; nt < 4; nt++) {
                int c0 = n0 + nt*8 + 2*(lane&3);
                bufF[c0*324 + r]         = C[mt][nt][0];
                bufF[(c0+1)*324 + r]     = C[mt][nt][1];
                bufF[c0*324 + r + 8]     = C[mt][nt][2];
                bufF[(c0+1)*324 + r + 8] = C[mt][nt][3];
            }
        }
        __syncthreads();
        const float* xl = x_l + cmb;
        float* ol = out_l + cmb;
        #pragma unroll
        for (int it = 0; it < 20; it++) {
            int e = it * 256 + tid, c = e / 80, w4 = e % 80;
            float bt = beta[c];
            float4 f = *(const float4*)(bufF + c*324 + w4*4);
            float4 xv = *(const float4*)(xl + (size_t)c*HWP + w4*4);
            float4 r = make_float4(xv.x + bt*f.x, xv.y + bt*f.y,
                                   xv.z + bt*f.z, xv.w + bt*f.w);
            *(float4*)(ol + (size_t)c*HWP + w4*4) = r;
        }
        __syncthreads();
    }

    // ---- GEMM3 (l2r): C[c][wr] = Vl @ (E*cinv) ----
    {
        const float* src = g_Vl + cmb;   // -> bufB [64][328]
        #pragma unroll
        for (int it = 0; it < 20; it++) {
            int e = it * 256 + tid, c = e / 80, w4 = e % 80;
            float4 v = *(const float4*)(src + (size_t)c * HWP + w4 * 4);
            *(uint4*)(bufB + c * 328 + w4 * 4) =
                make_uint4(f2tf(v.x), f2tf(v.y), f2tf(v.z), f2tf(v.w));
        }
        int wy = wid >> 2, wx = wid & 3;
        int m0 = wy * 32, n0 = wx * 80;
        float C[2][10][4];
        #pragma unroll
        for (int mt = 0; mt < 2; mt++)
            #pragma unroll
            for (int nt = 0; nt < 10; nt++)
                #pragma unroll
                for (int k = 0; k < 4; k++) C[mt][nt][k] = 0.f;

        for (int kc = 0; kc < 5; kc++) {
            #pragma unroll
            for (int it = 0; it < 20; it++) {   // E*cinv -> bufA [64][328]
                int e = it * 256 + tid, r = e / 80, w4 = e % 80;
                float4 v = *(const float4*)(Eb + (size_t)(kc*64 + r) * 320 + w4 * 4);
                int c0 = w4 * 4;
                *(uint4*)(bufA + r * 328 + w4 * 4) = make_uint4(
                    f2tf(v.x*cs[c0]), f2tf(v.y*cs[c0+1]),
                    f2tf(v.z*cs[c0+2]), f2tf(v.w*cs[c0+3]));
            }
            __syncthreads();
            #pragma unroll
            for (int ks = 0; ks < 8; ks++) {
                uint32_t a[2][4], bb[10][2];
                #pragma unroll
                for (int mt = 0; mt < 2; mt++) {
                    const uint32_t* p = bufB + (m0 + mt*16 + (lane>>2))*328 + kc*64 + ks*8 + (lane&3);
                    a[mt][0]=p[0]; a[mt][1]=p[8*328]; a[mt][2]=p[4]; a[mt][3]=p[8*328+4];
                }
                #pragma unroll
                for (int nt = 0; nt < 10; nt++) {
                    const uint32_t* p = bufA + (ks*8 + (lane&3))*328 + n0 + nt*8 + (lane>>2);
                    bb[nt][0]=p[0]; bb[nt][1]=p[4*328];
                }
                #pragma unroll
                for (int mt = 0; mt < 2; mt++)
                    #pragma unroll
                    for (int nt = 0; nt < 10; nt++)
                        mma_tf32(C[mt][nt], a[mt], bb[nt]);
            }
            __syncthreads();
        }
        const float* xr = x_r + cmb;
        float* orr = out_r + cmb;
        #pragma unroll
        for (int mt = 0; mt < 2; mt++) {
            int r = m0 + mt*16 + (lane>>2);
            float g0 = gamma[r], g1 = gamma[r + 8];
            #pragma unroll
            for (int nt = 0; nt < 10; nt++) {
                int c0 = n0 + nt*8 + 2*(lane&3);
                float2 x0 = *(const float2*)(xr + (size_t)r*HWP + c0);
                *(float2*)(orr + (size_t)r*HWP + c0) =
                    make_float2(x0.x + g0*C[mt][nt][0], x0.y + g0*C[mt][nt][1]);
                float2 x1 = *(const float2*)(xr + (size_t)(r+8)*HWP + c0);
                *(float2*)(orr + (size_t)(r+8)*HWP + c0) =
                    make_float2(x1.x + g1*C[mt][nt][2], x1.y + g1*C[mt][nt][3]);
            }
        }
    }
}

extern "C" void kernel_launch(void* const* d_in, const int* in_sizes, int n_in,
                              void* d_out, int out_size)
{
    const float* x_l    = (const float*)d_in[0];
    const float* x_r    = (const float*)d_in[1];
    const float* ln_l_w = (const float*)d_in[2];
    const float* ln_l_b = (const float*)d_in[3];
    const float* ln_r_w = (const float*)d_in[4];
    const float* ln_r_b = (const float*)d_in[5];
    const float* wq_l   = (const float*)d_in[6];
    const float* bq_l   = (const float*)d_in[7];
    const float* wq_r   = (const float*)d_in[8];
    const float* bq_r   = (const float*)d_in[9];
    const float* wv_l   = (const float*)d_in[10];
    const float* bv_l   = (const float*)d_in[11];
    const float* wv_r   = (const float*)d_in[12];
    const float* bv_r   = (const float*)d_in[13];
    const float* beta   = (const float*)d_in[14];
    const float* gamma  = (const float*)d_in[15];

    float* out_l = (float*)d_out;
    float* out_r = out_l + NELT;

    cudaFuncSetAttribute(fused_attn_kernel,
                         cudaFuncAttributeMaxDynamicSharedMemorySize, 176640);

    proj_kernel<<<NPIX/64, 256>>>(x_l, ln_l_w, ln_l_b, wq_l, bq_l, wv_l, bv_l, 0);
    proj_kernel<<<NPIX/64, 256>>>(x_r, ln_r_w, ln_r_b, wq_r, bq_r, wv_r, bv_r, 1);
    fused_attn_kernel<<<BB*HH, 256, 176640>>>(x_l, x_r, beta, gamma, out_l, out_r);
}

// round 6
// speedup vs baseline: 3.0995x; 1.1502x over previous
#include <cuda_runtime.h>
#include <cstdint>

#define BB   4
#define CCH  64
#define HH   180
#define WWD  320
#define HWP  (HH*WWD)
#define NPIX (BB*HWP)
#define NELT ((size_t)NPIX*CCH)

__device__ float g_QlT[(size_t)NPIX*CCH];   // [pix][c]
__device__ float g_Qr [(size_t)NPIX*CCH];   // [c][pix]
__device__ float g_Vl [(size_t)NPIX*CCH];   // [c][pix]
__device__ float g_VrT[(size_t)NPIX*CCH];   // [pix][c]
__device__ float g_E[(size_t)BB*HH*WWD*WWD];

__device__ __forceinline__ uint32_t f2tf(float x){
    uint32_t u; asm("cvt.rna.tf32.f32 %0, %1;" : "=r"(u) : "f"(x)); return u;
}
__device__ __forceinline__ void mma_tf32(float d[4], const uint32_t a[4], const uint32_t b[2]){
    asm volatile("mma.sync.aligned.m16n8k8.row.col.f32.tf32.tf32.f32 "
                 "{%0,%1,%2,%3}, {%4,%5,%6,%7}, {%8,%9}, {%0,%1,%2,%3};"
                 : "+f"(d[0]), "+f"(d[1]), "+f"(d[2]), "+f"(d[3])
                 : "r"(a[0]), "r"(a[1]), "r"(a[2]), "r"(a[3]), "r"(b[0]), "r"(b[1]));
}

// ---------------- projection via tensor cores ----------------
// Per block: 64-pixel tile. V = wv@x (raw), Q = wq@LN(x). tf32 mma.
// side 0: Q -> g_QlT [pix][c] (staged), V -> g_Vl [c][pix] (direct)
// side 1: Q -> g_Qr  [c][pix] (direct), V -> g_VrT [pix][c] (staged)
__global__ __launch_bounds__(256) void proj_mma_kernel(
    const float* __restrict__ x_l, const float* __restrict__ x_r,
    const float* __restrict__ lnw_l, const float* __restrict__ lnb_l,
    const float* __restrict__ lnw_r, const float* __restrict__ lnb_r,
    const float* __restrict__ wq_l,  const float* __restrict__ bq_l,
    const float* __restrict__ wq_r,  const float* __restrict__ bq_r,
    const float* __restrict__ wv_l,  const float* __restrict__ bv_l,
    const float* __restrict__ wv_r,  const float* __restrict__ bv_r)
{
    extern __shared__ float smf[];
    float*    xs = smf;                         // [64][68] raw x
    uint32_t* xt = (uint32_t*)(smf + 4352);     // [64][68] tf32 operand B
    uint32_t* wA = (uint32_t*)(smf + 8704);     // [64][68] tf32 operand A
    float*    mu_s = smf + 13056;               // [64]
    float*    rs_s = smf + 13120;               // [64]
    float*    stf  = (float*)xt;                // staging alias

    int side = blockIdx.x >= 3600;
    int blk  = blockIdx.x - side * 3600;

    const float* x   = side ? x_r   : x_l;
    const float* lnw = side ? lnw_r : lnw_l;
    const float* lnb = side ? lnb_r : lnb_l;
    const float* wq  = side ? wq_r  : wq_l;
    const float* bq  = side ? bq_r  : bq_l;
    const float* wv  = side ? wv_r  : wv_l;
    const float* bv  = side ? bv_r  : bv_l;
    float* Qo = side ? g_Qr  : g_QlT;
    float* Vo = side ? g_VrT : g_Vl;

    int tid = threadIdx.x, lane = tid & 31, wid = tid >> 5;
    int pb  = blk * 64;
    int b   = pb / HWP;
    int q0  = pb - b * HWP;
    const float* xb = x + ((size_t)b * CCH) * HWP + q0;

    // load x tile [c][p] and wv as A [o][c], both coalesced
    #pragma unroll
    for (int i = 0; i < 16; i++) {
        int idx = i * 256 + tid;
        int hi = idx >> 6, lo = idx & 63;
        xs[hi * 68 + lo] = xb[(size_t)hi * HWP + lo];
        wA[hi * 68 + lo] = f2tf(wv[idx]);
    }
    __syncthreads();

    // LN stats per pixel + raw-x tf32 conversion
    if (tid < 64) {
        float s = 0.f, ss = 0.f;
        #pragma unroll
        for (int c = 0; c < 64; c++) { float v = xs[c * 68 + tid]; s += v; ss += v*v; }
        float m = s * 0.015625f;
        mu_s[tid] = m;
        rs_s[tid] = rsqrtf(ss * 0.015625f - m*m + 1e-6f);
    }
    #pragma unroll
    for (int i = 0; i < 16; i++) {
        int idx = i * 256 + tid;
        int c = idx >> 6, p = idx & 63;
        xt[c * 68 + p] = f2tf(xs[c * 68 + p]);
    }
    __syncthreads();

    int wy = wid >> 1, wx = wid & 1;
    int m0 = wy * 16, n0 = wx * 32;

    // ---- V GEMM: C[o][p] = wv @ x ----
    float Cv[4][4];
    #pragma unroll
    for (int nt = 0; nt < 4; nt++)
        #pragma unroll
        for (int k = 0; k < 4; k++) Cv[nt][k] = 0.f;
    #pragma unroll
    for (int ks = 0; ks < 8; ks++) {
        uint32_t a[4], bbr[2];
        const uint32_t* pA = wA + (m0 + (lane>>2)) * 68 + ks*8 + (lane&3);
        a[0]=pA[0]; a[1]=pA[8*68]; a[2]=pA[4]; a[3]=pA[8*68+4];
        #pragma unroll
        for (int nt = 0; nt < 4; nt++) {
            const uint32_t* pB = xt + (ks*8 + (lane&3)) * 68 + n0 + nt*8 + (lane>>2);
            bbr[0]=pB[0]; bbr[1]=pB[4*68];
            mma_tf32(Cv[nt], a, bbr);
        }
    }

    int r = m0 + (lane>>2);
    if (side == 0) {
        // direct channel-major write
        float b0 = bv[r], b1 = bv[r + 8];
        #pragma unroll
        for (int nt = 0; nt < 4; nt++) {
            int p = n0 + nt*8 + 2*(lane&3);
            *(float2*)&Vo[((size_t)(b*CCH + r)) * HWP + q0 + p] =
                make_float2(Cv[nt][0] + b0, Cv[nt][1] + b0);
            *(float2*)&Vo[((size_t)(b*CCH + r + 8)) * HWP + q0 + p] =
                make_float2(Cv[nt][2] + b1, Cv[nt][3] + b1);
        }
        __syncthreads();
    } else {
        // staged [pix][c] write
        __syncthreads();
        #pragma unroll
        for (int nt = 0; nt < 4; nt++) {
            int p = n0 + nt*8 + 2*(lane&3);
            stf[p * 68 + r]           = Cv[nt][0];
            stf[(p + 1) * 68 + r]     = Cv[nt][1];
            stf[p * 68 + r + 8]       = Cv[nt][2];
            stf[(p + 1) * 68 + r + 8] = Cv[nt][3];
        }
        __syncthreads();
        #pragma unroll
        for (int i = 0; i < 4; i++) {
            int idx = i * 256 + tid;
            int p = idx >> 4, c4 = idx & 15;
            float4 v = *(const float4*)(stf + p * 68 + c4 * 4);
            float4 bb4 = *(const float4*)(bv + c4 * 4);
            *(float4*)&Vo[((size_t)pb + p) * 64 + c4 * 4] =
                make_float4(v.x + bb4.x, v.y + bb4.y, v.z + bb4.z, v.w + bb4.w);
        }
        __syncthreads();
    }

    // swap to Q operands: wA = tf32(wq), xt = tf32(LN(x))
    #pragma unroll
    for (int i = 0; i < 16; i++) {
        int idx = i * 256 + tid;
        wA[(idx >> 6) * 68 + (idx & 63)] = f2tf(wq[idx]);
    }
    #pragma unroll
    for (int i = 0; i < 16; i++) {
        int idx = i * 256 + tid;
        int c = idx >> 6, p = idx & 63;
        xt[c * 68 + p] = f2tf((xs[c * 68 + p] - mu_s[p]) * rs_s[p] * lnw[c] + lnb[c]);
    }
    __syncthreads();

    // ---- Q GEMM: C[o][p] = wq @ LN(x) ----
    float Cq[4][4];
    #pragma unroll
    for (int nt = 0; nt < 4; nt++)
        #pragma unroll
        for (int k = 0; k < 4; k++) Cq[nt][k] = 0.f;
    #pragma unroll
    for (int ks = 0; ks < 8; ks++) {
        uint32_t a[4], bbr[2];
        const uint32_t* pA = wA + (m0 + (lane>>2)) * 68 + ks*8 + (lane&3);
        a[0]=pA[0]; a[1]=pA[8*68]; a[2]=pA[4]; a[3]=pA[8*68+4];
        #pragma unroll
        for (int nt = 0; nt < 4; nt++) {
            const uint32_t* pB = xt + (ks*8 + (lane&3)) * 68 + n0 + nt*8 + (lane>>2);
            bbr[0]=pB[0]; bbr[1]=pB[4*68];
            mma_tf32(Cq[nt], a, bbr);
        }
    }

    if (side == 1) {
        float b0 = bq[r], b1 = bq[r + 8];
        #pragma unroll
        for (int nt = 0; nt < 4; nt++) {
            int p = n0 + nt*8 + 2*(lane&3);
            *(float2*)&Qo[((size_t)(b*CCH + r)) * HWP + q0 + p] =
                make_float2(Cq[nt][0] + b0, Cq[nt][1] + b0);
            *(float2*)&Qo[((size_t)(b*CCH + r + 8)) * HWP + q0 + p] =
                make_float2(Cq[nt][2] + b1, Cq[nt][3] + b1);
        }
    } else {
        __syncthreads();
        #pragma unroll
        for (int nt = 0; nt < 4; nt++) {
            int p = n0 + nt*8 + 2*(lane&3);
            stf[p * 68 + r]           = Cq[nt][0];
            stf[(p + 1) * 68 + r]     = Cq[nt][1];
            stf[p * 68 + r + 8]       = Cq[nt][2];
            stf[(p + 1) * 68 + r + 8] = Cq[nt][3];
        }
        __syncthreads();
        #pragma unroll
        for (int i = 0; i < 4; i++) {
            int idx = i * 256 + tid;
            int p = idx >> 4, c4 = idx & 15;
            float4 v = *(const float4*)(stf + p * 68 + c4 * 4);
            float4 bb4 = *(const float4*)(bq + c4 * 4);
            *(float4*)&Qo[((size_t)pb + p) * 64 + c4 * 4] =
                make_float4(v.x + bb4.x, v.y + bb4.y, v.z + bb4.z, v.w + bb4.w);
        }
    }
}

// ---------------- fused attention per (b,h) ----------------
__global__ __launch_bounds__(256, 1) void fused_attn_kernel(
    const float* __restrict__ x_l, const float* __restrict__ x_r,
    const float* __restrict__ beta, const float* __restrict__ gamma,
    float* __restrict__ out_l, float* __restrict__ out_r)
{
    extern __shared__ float sm[];
    float* rs = sm;                 // [320]
    float* cs = sm + 320;           // [320]
    uint32_t* bufA = (uint32_t*)(sm + 640);   // 21760
    uint32_t* bufB = bufA + 21760;            // 21760

    int tid = threadIdx.x, lane = tid & 31, wid = tid >> 5;
    int bh = blockIdx.x, b = bh / HH, h = bh - b * HH;
    size_t pixb = (size_t)b * HWP + h * WWD;
    size_t cmb  = (size_t)b * CCH * HWP + h * WWD;
    float* Eb = g_E + (size_t)bh * (WWD * WWD);

    for (int i = tid; i < 640; i += 256) sm[i] = 0.f;

    { // QlT -> bufA [320][68]
        const float* src = g_QlT + pixb * 64;
        #pragma unroll
        for (int it = 0; it < 20; it++) {
            int e = it * 256 + tid, wl = e >> 4, c4 = e & 15;
            float4 v = *(const float4*)(src + (size_t)wl * 64 + c4 * 4);
            *(uint4*)(bufA + wl * 68 + c4 * 4) =
                make_uint4(f2tf(v.x), f2tf(v.y), f2tf(v.z), f2tf(v.w));
        }
    }
    { // Qr -> bufB [64][328]
        const float* src = g_Qr + cmb;
        #pragma unroll
        for (int it = 0; it < 20; it++) {
            int e = it * 256 + tid, c = e / 80, w4 = e % 80;
            float4 v = *(const float4*)(src + (size_t)c * HWP + w4 * 4);
            *(uint4*)(bufB + c * 328 + w4 * 4) =
                make_uint4(f2tf(v.x), f2tf(v.y), f2tf(v.z), f2tf(v.w));
        }
    }
    __syncthreads();

    // ---- GEMM1: E = exp(0.125 * Ql^T Qr), row/col sums ----
    {
        int wy = wid >> 2, wx = wid & 3, n0 = wx * 80;
        for (int mb = 0; mb < 5; mb++) {
            int m0 = mb * 64 + wy * 32;
            float C[2][10][4];
            #pragma unroll
            for (int mt = 0; mt < 2; mt++)
                #pragma unroll
                for (int nt = 0; nt < 10; nt++)
                    #pragma unroll
                    for (int k = 0; k < 4; k++) C[mt][nt][k] = 0.f;
            #pragma unroll
            for (int ks = 0; ks < 8; ks++) {
                uint32_t a[2][4], bb[10][2];
                #pragma unroll
                for (int mt = 0; mt < 2; mt++) {
                    const uint32_t* p = bufA + (m0 + mt*16 + (lane>>2))*68 + ks*8 + (lane&3);
                    a[mt][0]=p[0]; a[mt][1]=p[8*68]; a[mt][2]=p[4]; a[mt][3]=p[8*68+4];
                }
                #pragma unroll
                for (int nt = 0; nt < 10; nt++) {
                    const uint32_t* p = bufB + (ks*8 + (lane&3))*328 + n0 + nt*8 + (lane>>2);
                    bb[nt][0]=p[0]; bb[nt][1]=p[4*328];
                }
                #pragma unroll
                for (int mt = 0; mt < 2; mt++)
                    #pragma unroll
                    for (int nt = 0; nt < 10; nt++)
                        mma_tf32(C[mt][nt], a[mt], bb[nt]);
            }
            #pragma unroll
            for (int mt = 0; mt < 2; mt++)
                #pragma unroll
                for (int nt = 0; nt < 10; nt++)
                    #pragma unroll
                    for (int k = 0; k < 4; k++)
                        C[mt][nt][k] = __expf(C[mt][nt][k] * 0.125f);
            #pragma unroll
            for (int mt = 0; mt < 2; mt++) {
                int r0 = m0 + mt*16 + (lane>>2);
                float s0 = 0.f, s1 = 0.f;
                #pragma unroll
                for (int nt = 0; nt < 10; nt++) {
                    int col = n0 + nt*8 + 2*(lane&3);
                    float2 lo = make_float2(C[mt][nt][0], C[mt][nt][1]);
                    float2 hi = make_float2(C[mt][nt][2], C[mt][nt][3]);
                    *(float2*)(Eb + (size_t)r0*320 + col)     = lo;
                    *(float2*)(Eb + (size_t)(r0+8)*320 + col) = hi;
                    s0 += lo.x + lo.y; s1 += hi.x + hi.y;
                }
                s0 += __shfl_xor_sync(~0u, s0, 1); s0 += __shfl_xor_sync(~0u, s0, 2);
                s1 += __shfl_xor_sync(~0u, s1, 1); s1 += __shfl_xor_sync(~0u, s1, 2);
                if ((lane & 3) == 0) { atomicAdd(&rs[r0], s0); atomicAdd(&rs[r0+8], s1); }
            }
            #pragma unroll
            for (int nt = 0; nt < 10; nt++) {
                int col = n0 + nt*8 + 2*(lane&3);
                float v0 = C[0][nt][0]+C[0][nt][2]+C[1][nt][0]+C[1][nt][2];
                float v1 = C[0][nt][1]+C[0][nt][3]+C[1][nt][1]+C[1][nt][3];
                v0 += __shfl_xor_sync(~0u, v0, 4); v0 += __shfl_xor_sync(~0u, v0, 8); v0 += __shfl_xor_sync(~0u, v0, 16);
                v1 += __shfl_xor_sync(~0u, v1, 4); v1 += __shfl_xor_sync(~0u, v1, 8); v1 += __shfl_xor_sync(~0u, v1, 16);
                if ((lane >> 2) == 0) { atomicAdd(&cs[col], v0); atomicAdd(&cs[col+1], v1); }
            }
        }
    }
    __syncthreads();
    for (int i = tid; i < 640; i += 256) sm[i] = 1.0f / sm[i];
    __syncthreads();

    // ---- GEMM2 (r2l): C[wl][c] = (E*rinv) @ VrT ----
    {
        const float* src = g_VrT + pixb * 64;
        #pragma unroll
        for (int it = 0; it < 20; it++) {
            int e = it * 256 + tid, w = e >> 4, c4 = e & 15;
            float4 v = *(const float4*)(src + (size_t)w * 64 + c4 * 4);
            *(uint4*)(bufB + w * 68 + c4 * 4) =
                make_uint4(f2tf(v.x), f2tf(v.y), f2tf(v.z), f2tf(v.w));
        }
        int wy = wid >> 1, wx = wid & 1;
        int m0 = wy * 80, n0 = wx * 32;
        float C[5][4][4];
        #pragma unroll
        for (int mt = 0; mt < 5; mt++)
            #pragma unroll
            for (int nt = 0; nt < 4; nt++)
                #pragma unroll
                for (int k = 0; k < 4; k++) C[mt][nt][k] = 0.f;

        for (int kc = 0; kc < 5; kc++) {
            #pragma unroll
            for (int it = 0; it < 20; it++) {
                int e = it * 256 + tid, wl = e >> 4, c4 = e & 15;
                float4 v = *(const float4*)(Eb + (size_t)wl * 320 + kc*64 + c4*4);
                float ri = rs[wl];
                *(uint4*)(bufA + wl * 68 + c4 * 4) = make_uint4(
                    f2tf(v.x*ri), f2tf(v.y*ri), f2tf(v.z*ri), f2tf(v.w*ri));
            }
            __syncthreads();
            #pragma unroll
            for (int ks = 0; ks < 8; ks++) {
                uint32_t a[5][4], bb[4][2];
                #pragma unroll
                for (int mt = 0; mt < 5; mt++) {
                    const uint32_t* p = bufA + (m0 + mt*16 + (lane>>2))*68 + ks*8 + (lane&3);
                    a[mt][0]=p[0]; a[mt][1]=p[8*68]; a[mt][2]=p[4]; a[mt][3]=p[8*68+4];
                }
                #pragma unroll
                for (int nt = 0; nt < 4; nt++) {
                    const uint32_t* p = bufB + (kc*64 + ks*8 + (lane&3))*68 + n0 + nt*8 + (lane>>2);
                    bb[nt][0]=p[0]; bb[nt][1]=p[4*68];
                }
                #pragma unroll
                for (int mt = 0; mt < 5; mt++)
                    #pragma unroll
                    for (int nt = 0; nt < 4; nt++)
                        mma_tf32(C[mt][nt], a[mt], bb[nt]);
            }
            __syncthreads();
        }
        float* bufF = (float*)bufA;
        #pragma unroll
        for (int mt = 0; mt < 5; mt++) {
            int r = m0 + mt*16 + (lane>>2);
            #pragma unroll
            for (int nt = 0; nt < 4; nt++) {
                int c0 = n0 + nt*8 + 2*(lane&3);
                bufF[c0*324 + r]         = C[mt][nt][0];
                bufF[(c0+1)*324 + r]     = C[mt][nt][1];
                bufF[c0*324 + r + 8]     = C[mt][nt][2];
                bufF[(c0+1)*324 + r + 8] = C[mt][nt][3];
            }
        }
        __syncthreads();
        const float* xl = x_l + cmb;
        float* ol = out_l + cmb;
        #pragma unroll
        for (int it = 0; it < 20; it++) {
            int e = it * 256 + tid, c = e / 80, w4 = e % 80;
            float bt = beta[c];
            float4 f = *(const float4*)(bufF + c*324 + w4*4);
            float4 xv = *(const float4*)(xl + (size_t)c*HWP + w4*4);
            *(float4*)(ol + (size_t)c*HWP + w4*4) = make_float4(
                xv.x + bt*f.x, xv.y + bt*f.y, xv.z + bt*f.z, xv.w + bt*f.w);
        }
        __syncthreads();
    }

    // ---- GEMM3 (l2r): C[c][wr] = Vl @ (E*cinv) ----
    {
        const float* src = g_Vl + cmb;
        #pragma unroll
        for (int it = 0; it < 20; it++) {
            int e = it * 256 + tid, c = e / 80, w4 = e % 80;
            float4 v = *(const float4*)(src + (size_t)c * HWP + w4 * 4);
            *(uint4*)(bufB + c * 328 + w4 * 4) =
                make_uint4(f2tf(v.x), f2tf(v.y), f2tf(v.z), f2tf(v.w));
        }
        int wy = wid >> 2, wx = wid & 3;
        int m0 = wy * 32, n0 = wx * 80;
        float C[2][10][4];
        #pragma unroll
        for (int mt = 0; mt < 2; mt++)
            #pragma unroll
            for (int nt = 0; nt < 10; nt++)
                #pragma unroll
                for (int k = 0; k < 4; k++) C[mt][nt][k] = 0.f;

        for (int kc = 0; kc < 5; kc++) {
            #pragma unroll
            for (int it = 0; it < 20; it++) {
                int e = it * 256 + tid, r = e / 80, w4 = e % 80;
                float4 v = *(const float4*)(Eb + (size_t)(kc*64 + r) * 320 + w4 * 4);
                int c0 = w4 * 4;
                *(uint4*)(bufA + r * 328 + w4 * 4) = make_uint4(
                    f2tf(v.x*cs[c0]), f2tf(v.y*cs[c0+1]),
                    f2tf(v.z*cs[c0+2]), f2tf(v.w*cs[c0+3]));
            }
            __syncthreads();
            #pragma unroll
            for (int ks = 0; ks < 8; ks++) {
                uint32_t a[2][4], bb[10][2];
                #pragma unroll
                for (int mt = 0; mt < 2; mt++) {
                    const uint32_t* p = bufB + (m0 + mt*16 + (lane>>2))*328 + kc*64 + ks*8 + (lane&3);
                    a[mt][0]=p[0]; a[mt][1]=p[8*328]; a[mt][2]=p[4]; a[mt][3]=p[8*328+4];
                }
                #pragma unroll
                for (int nt = 0; nt < 10; nt++) {
                    const uint32_t* p = bufA + (ks*8 + (lane&3))*328 + n0 + nt*8 + (lane>>2);
                    bb[nt][0]=p[0]; bb[nt][1]=p[4*328];
                }
                #pragma unroll
                for (int mt = 0; mt < 2; mt++)
                    #pragma unroll
                    for (int nt = 0; nt < 10; nt++)
                        mma_tf32(C[mt][nt], a[mt], bb[nt]);
            }
            __syncthreads();
        }
        const float* xr = x_r + cmb;
        float* orr = out_r + cmb;
        #pragma unroll
        for (int mt = 0; mt < 2; mt++) {
            int r = m0 + mt*16 + (lane>>2);
            float g0 = gamma[r], g1 = gamma[r + 8];
            #pragma unroll
            for (int nt = 0; nt < 10; nt++) {
                int c0 = n0 + nt*8 + 2*(lane&3);
                float2 x0 = *(const float2*)(xr + (size_t)r*HWP + c0);
                *(float2*)(orr + (size_t)r*HWP + c0) =
                    make_float2(x0.x + g0*C[mt][nt][0], x0.y + g0*C[mt][nt][1]);
                float2 x1 = *(const float2*)(xr + (size_t)(r+8)*HWP + c0);
                *(float2*)(orr + (size_t)(r+8)*HWP + c0) =
                    make_float2(x1.x + g1*C[mt][nt][2], x1.y + g1*C[mt][nt][3]);
            }
        }
    }
}

extern "C" void kernel_launch(void* const* d_in, const int* in_sizes, int n_in,
                              void* d_out, int out_size)
{
    const float* x_l    = (const float*)d_in[0];
    const float* x_r    = (const float*)d_in[1];
    const float* ln_l_w = (const float*)d_in[2];
    const float* ln_l_b = (const float*)d_in[3];
    const float* ln_r_w = (const float*)d_in[4];
    const float* ln_r_b = (const float*)d_in[5];
    const float* wq_l   = (const float*)d_in[6];
    const float* bq_l   = (const float*)d_in[7];
    const float* wq_r   = (const float*)d_in[8];
    const float* bq_r   = (const float*)d_in[9];
    const float* wv_l   = (const float*)d_in[10];
    const float* bv_l   = (const float*)d_in[11];
    const float* wv_r   = (const float*)d_in[12];
    const float* bv_r   = (const float*)d_in[13];
    const float* beta   = (const float*)d_in[14];
    const float* gamma  = (const float*)d_in[15];

    float* out_l = (float*)d_out;
    float* out_r = out_l + NELT;

    cudaFuncSetAttribute(proj_mma_kernel,
                         cudaFuncAttributeMaxDynamicSharedMemorySize, 52736);
    cudaFuncSetAttribute(fused_attn_kernel,
                         cudaFuncAttributeMaxDynamicSharedMemorySize, 176640);

    proj_mma_kernel<<<7200, 256, 52736>>>(
        x_l, x_r, ln_l_w, ln_l_b, ln_r_w, ln_r_b,
        wq_l, bq_l, wq_r, bq_r, wv_l, bv_l, wv_r, bv_r);
    fused_attn_kernel<<<BB*HH, 256, 176640>>>(x_l, x_r, beta, gamma, out_l, out_r);
}